// round 13
// baseline (speedup 1.0000x reference)
#include <cuda_runtime.h>
#include <cstdint>

// B=4, M_IN=16, M_OUT=32, C=32.  x:(4,16,32,32,32,32) fp32 -> out:(4,32,4,32) fp32
//
//   s1[b,m,c2] = sum_{c3,c4,c5} x          (s2 == s1)
//   s3[b,m,c3] = sum_{c2,c4,c5} x
//   s4[b,m,c4] = sum_{c2,c3,c5} x
//   W = alpha+beta+gamma+delta (16x32)
//   out[b,n,i,c] = sum_m S_i[b,m,c] * W[m,n],  S = [s1,s1,s3,s4]
//
// Kernel 1 (4096 blocks): R3-proven plain-store stream (fastest measured,
//   ~37.9us). Block 0 additionally precomputes g_W (L2-hot for the tail).
// Kernel 2 (64 blocks, (b,i,oct)): R3-proven stage A + einsum, W from hot g_W.

__device__ float g_s1h[4096];            // [bid], bid = slice*2+half, slice=(b*16+m)*32+c2
__device__ float g_s3 [2048 * 32];       // [slice][c3]  (full over c4,c5; unique owner half)
__device__ float g_s4h[4096 * 32];       // [bid][c4]    (partial over this half's c3)
__device__ float g_W  [512];             // [m][n] = a+b+g+d (written by block 0, wave 1)

__device__ __forceinline__ unsigned long long addx2(unsigned long long a,
                                                    unsigned long long b) {
    unsigned long long r;
    asm("add.rn.f32x2 %0, %1, %2;" : "=l"(r) : "l"(a), "l"(b));
    return r;
}
__device__ __forceinline__ float x2sum(unsigned long long a) {
    unsigned lo, hi;
    asm("mov.b64 {%0,%1}, %2;" : "=r"(lo), "=r"(hi) : "l"(a));
    return __uint_as_float(lo) + __uint_as_float(hi);
}
// evict-first 16B streaming load (read-once data; keep L2 for partials)
__device__ __forceinline__ ulonglong2 ldcs2(const ulonglong2* p) {
    ulonglong2 r;
    asm("ld.global.cs.v2.u64 {%0, %1}, [%2];" : "=l"(r.x), "=l"(r.y) : "l"(p));
    return r;
}

// ---------------- Kernel 1: half-slice reduction (R3, verbatim) + g_W precompute ----------
__global__ void __launch_bounds__(256, 4)
k_reduce(const float* __restrict__ x,
         const float* __restrict__ wa, const float* __restrict__ wb,
         const float* __restrict__ wg, const float* __restrict__ wd) {
    const int t    = threadIdx.x;
    const int lane = t & 31;
    const int w    = t >> 5;
    const int bid  = blockIdx.x;          // half-slice id
    const int slice = bid >> 1;
    const int half  = bid & 1;

    // block 0: W precompute (runs in wave 1; hot in L2 long before the tail)
    if (bid == 0) {
        g_W[t]       = wa[t]       + wb[t]       + wg[t]       + wd[t];
        g_W[t + 256] = wa[t + 256] + wb[t + 256] + wg[t + 256] + wd[t + 256];
    }

    const ulonglong2* __restrict__ xv =
        reinterpret_cast<const ulonglong2*>(x) + (size_t)bid * 4096; // 16384 floats

    __shared__ float s4buf[256];          // [warp][c4]
    __shared__ float wt[8];

    unsigned long long col[8];
#pragma unroll
    for (int s = 0; s < 8; ++s) col[s] = 0ull;

    float rows_tot = 0.f;                 // valid on lane 0
#pragma unroll
    for (int j = 0; j < 2; ++j) {
        const int k = w + j * 8;          // local row 0..15  (c3 = half*16 + k)
        const ulonglong2* __restrict__ p = xv + k * 256 + lane;

        ulonglong2 d[8];
#pragma unroll
        for (int s = 0; s < 8; ++s) d[s] = ldcs2(p + s * 32);   // 8 back-to-back LDG.128

        unsigned long long row = 0ull;
#pragma unroll
        for (int s = 0; s < 8; ++s) {
            unsigned long long v = addx2(d[s].x, d[s].y);  // {f0+f2, f1+f3}
            row    = addx2(row, v);
            col[s] = addx2(col[s], v);
        }
        float r = x2sum(row);
#pragma unroll
        for (int o = 16; o; o >>= 1) r += __shfl_down_sync(0xffffffffu, r, o);
        if (lane == 0) {
            g_s3[slice * 32 + half * 16 + k] = r;   // full s3 entry (unique owner)
            rows_tot += r;
        }
    }

#pragma unroll
    for (int s = 0; s < 8; ++s) {
        float cs = x2sum(col[s]);
        cs += __shfl_down_sync(0xffffffffu, cs, 4);
        cs += __shfl_down_sync(0xffffffffu, cs, 2);
        cs += __shfl_down_sync(0xffffffffu, cs, 1);
        if ((lane & 7) == 0) s4buf[w * 32 + s * 4 + (lane >> 3)] = cs;
    }
    if (lane == 0) wt[w] = rows_tot;
    __syncthreads();

    if (t < 32) {        // warp 0: cross-warp s4 fold + slice total
        float v = 0.f;
#pragma unroll
        for (int ww = 0; ww < 8; ++ww) v += s4buf[ww * 32 + t];
        g_s4h[bid * 32 + t] = v;
        if (t == 0) {
            float s = 0.f;
#pragma unroll
            for (int ww = 0; ww < 8; ++ww) s += wt[ww];
            g_s1h[bid] = s;
        }
    }
}

// ---------------- Kernel 2: tail (R3 structure), W from hot g_W ----------------
// block bid: b = bid>>4, i = (bid>>2)&3, oct = bid&3 (c in [oct*8, oct*8+8))
__global__ void __launch_bounds__(256)
k_tail(float* __restrict__ out) {
    __shared__ float sW[512];             // [m][n]
    __shared__ float pp[256];
    __shared__ float sS[128];             // [m][cl]

    const int t   = threadIdx.x;
    const int bid = blockIdx.x;
    const int b   = bid >> 4;
    const int i   = (bid >> 2) & 3;
    const int oct = bid & 3;

    sW[t]       = g_W[t];                 // L2-hot (written in wave 1)
    sW[t + 256] = g_W[t + 256];

    // ---- stage A: build S[m][cl] (2 threads per value; R3-proven) ----
    const int pair = t >> 1;              // 0..127
    const int part = t & 1;
    const int m    = pair >> 3;           // 0..15
    const int cl   = pair & 7;
    const int c    = oct * 8 + cl;
    const int bm   = b * 16 + m;

    float v = 0.f;
    if (i < 2) {
        v = g_s1h[(bm * 32 + c) * 2 + part];           // c plays c2; part = half
    } else if (i == 2) {
        const float* __restrict__ p = g_s3 + bm * 1024 + (part * 16) * 32 + c;
#pragma unroll
        for (int q = 0; q < 16; ++q) v += p[q * 32];   // over c2
    } else {
        const float* __restrict__ p = g_s4h + bm * 2048 + (part * 32) * 32 + c;
#pragma unroll
        for (int q = 0; q < 32; ++q) v += p[q * 32];   // over (c2,half)
    }
    pp[t] = v;
    __syncthreads();
    if (t < 128) sS[t] = pp[2 * t] + pp[2 * t + 1];
    __syncthreads();

    // ---- stage B: out[b,n,i,c] = sum_m S[m][cl] * W[m,n] ----
    const int n  = t >> 3;                // 0..31
    const int c2 = t & 7;                 // cl
    float acc = 0.f;
#pragma unroll
    for (int mm = 0; mm < 16; ++mm)
        acc += sS[mm * 8 + c2] * sW[mm * 32 + n];
    out[((b * 32 + n) * 4 + i) * 32 + oct * 8 + c2] = acc;
}

// ---------------- launch ----------------
extern "C" void kernel_launch(void* const* d_in, const int* in_sizes, int n_in,
                              void* d_out, int out_size) {
    const float* x     = (const float*)d_in[0];
    const float* alpha = (const float*)d_in[1];
    const float* beta  = (const float*)d_in[2];
    const float* gamma = (const float*)d_in[3];
    const float* delta = (const float*)d_in[4];

    k_reduce<<<4096, 256>>>(x, alpha, beta, gamma, delta);
    k_tail  <<<64, 256>>>((float*)d_out);
}

// round 14
// speedup vs baseline: 1.0142x; 1.0142x over previous
#include <cuda_runtime.h>
#include <cstdint>

// B=4, M_IN=16, M_OUT=32, C=32.  x:(4,16,32,32,32,32) fp32 -> out:(4,32,4,32) fp32
//
//   s1[b,m,c2] = sum_{c3,c4,c5} x          (s2 == s1)
//   s3[b,m,c3] = sum_{c2,c4,c5} x
//   s4[b,m,c4] = sum_{c2,c3,c5} x
//   W = alpha+beta+gamma+delta (16x32)
//   out[b,n,i,c] = sum_m S_i[b,m,c] * W[m,n],  S = [s1,s1,s3,s4]
//
// SINGLE launch, grid 4100:
//   bids 0..4095 : R10/R12-proven stream: half-slice reduction, REDG
//     epilogue into g_S[bm][i][c] (~50 fire-and-forget red.add, proven ~free).
//     Block 0 also precomputes g_W. Each block signals completion with
//     t0: threadfence + red.relaxed(g_cnt)  (R5==R6 proved the fence is free).
//   bids 4096..4099 : einsum spinners (one per b), scheduled in the LAST
//     wave (0.7% worst-case slot theft). Poll g_cnt==4096 (acquire+nanosleep),
//     snapshot L2-hot g_S[b] -> smem, self-zero it, einsum vs hot g_W,
//     write out. Counter reset handshake via g_fin. No second launch.

__device__ float g_S[8192];              // [bm][i][c], REDG-accumulated (zero at load)
__device__ float g_W[512];               // [m][n] = a+b+g+d (block 0, wave 1)
__device__ int   g_cnt;                  // stream blocks completed
__device__ int   g_fin;                  // spinners past the wait

__device__ __forceinline__ unsigned long long addx2(unsigned long long a,
                                                    unsigned long long b) {
    unsigned long long r;
    asm("add.rn.f32x2 %0, %1, %2;" : "=l"(r) : "l"(a), "l"(b));
    return r;
}
__device__ __forceinline__ float x2sum(unsigned long long a) {
    unsigned lo, hi;
    asm("mov.b64 {%0,%1}, %2;" : "=r"(lo), "=r"(hi) : "l"(a));
    return __uint_as_float(lo) + __uint_as_float(hi);
}
__device__ __forceinline__ ulonglong2 ldcs2(const ulonglong2* p) {
    ulonglong2 r;
    asm("ld.global.cs.v2.u64 {%0, %1}, [%2];" : "=l"(r.x), "=l"(r.y) : "l"(p));
    return r;
}
__device__ __forceinline__ void red_add(float* p, float v) {
    asm volatile("red.global.add.f32 [%0], %1;" :: "l"(p), "f"(v) : "memory");
}
__device__ __forceinline__ void red_inc(int* p) {
    asm volatile("red.relaxed.gpu.global.add.s32 [%0], 1;" :: "l"(p) : "memory");
}
__device__ __forceinline__ int ld_acquire(const int* p) {
    int v;
    asm volatile("ld.acquire.gpu.global.s32 %0, [%1];" : "=r"(v) : "l"(p) : "memory");
    return v;
}

__global__ void __launch_bounds__(256, 4)
k_all(const float* __restrict__ x,
      const float* __restrict__ wa, const float* __restrict__ wb,
      const float* __restrict__ wg, const float* __restrict__ wd,
      float* __restrict__ out) {
    const int t    = threadIdx.x;
    const int lane = t & 31;
    const int w    = t >> 5;
    const int bid  = blockIdx.x;

    if (bid < 4096) {
        // ================= stream path (R10/R12-proven) =================
        const int slice = bid >> 1;
        const int half  = bid & 1;
        const int bm    = bid >> 6;

        if (bid == 0) {   // W precompute, wave 1 -> L2-hot for spinners
            g_W[t]       = wa[t]       + wb[t]       + wg[t]       + wd[t];
            g_W[t + 256] = wa[t + 256] + wb[t + 256] + wg[t + 256] + wd[t + 256];
        }

        const ulonglong2* __restrict__ xv =
            reinterpret_cast<const ulonglong2*>(x) + (size_t)bid * 4096;

        __shared__ float s4buf[256];
        __shared__ float wt[8];

        unsigned long long col[8];
#pragma unroll
        for (int s = 0; s < 8; ++s) col[s] = 0ull;

        float rows_tot = 0.f;             // valid on lane 0
#pragma unroll
        for (int j = 0; j < 2; ++j) {
            const int k = w + j * 8;      // c3 = half*16 + k
            const ulonglong2* __restrict__ p = xv + k * 256 + lane;

            ulonglong2 d[8];
#pragma unroll
            for (int s = 0; s < 8; ++s) d[s] = ldcs2(p + s * 32);

            unsigned long long row = 0ull;
#pragma unroll
            for (int s = 0; s < 8; ++s) {
                unsigned long long v = addx2(d[s].x, d[s].y);
                row    = addx2(row, v);
                col[s] = addx2(col[s], v);
            }
            float r = x2sum(row);
#pragma unroll
            for (int o = 16; o; o >>= 1) r += __shfl_down_sync(0xffffffffu, r, o);
            if (lane == 0) {
                red_add(&g_S[bm * 128 + 64 + half * 16 + k], r);   // s3
                rows_tot += r;
            }
        }

#pragma unroll
        for (int s = 0; s < 8; ++s) {
            float cs = x2sum(col[s]);
            cs += __shfl_down_sync(0xffffffffu, cs, 4);
            cs += __shfl_down_sync(0xffffffffu, cs, 2);
            cs += __shfl_down_sync(0xffffffffu, cs, 1);
            if ((lane & 7) == 0) s4buf[w * 32 + s * 4 + (lane >> 3)] = cs;
        }
        if (lane == 0) wt[w] = rows_tot;
        __syncthreads();

        if (t < 32) {
            float v = 0.f;
#pragma unroll
            for (int ww = 0; ww < 8; ++ww) v += s4buf[ww * 32 + t];
            red_add(&g_S[bm * 128 + 96 + t], v);                   // s4
            if (t == 0) {
                float s = 0.f;
#pragma unroll
                for (int ww = 0; ww < 8; ++ww) s += wt[ww];
                const int c2 = slice & 31;
                red_add(&g_S[bm * 128 +      c2], s);              // s1
                red_add(&g_S[bm * 128 + 32 + c2], s);              // s2 == s1
            }
        }
        __syncthreads();
        if (t == 0) {
            __threadfence();              // proven free (R5==R6); orders REDGs
            red_inc(&g_cnt);
        }
        return;
    }

    // ================= spinner path: b = bid - 4096 =================
    const int b = bid - 4096;
    __shared__ float sS[2048];            // [m][i][c] for this b
    __shared__ float sW[512];

    if (t == 0) {
        while (ld_acquire(&g_cnt) < 4096) __nanosleep(64);
    }
    __syncthreads();                      // all partials + g_W visible

    // snapshot (8 floats/thread, contiguous) + self-zero own addresses
    {
        float4* src = reinterpret_cast<float4*>(&g_S[b * 2048]) + t * 2;
        float4 v0 = src[0], v1 = src[1];
        reinterpret_cast<float4*>(sS)[t * 2]     = v0;
        reinterpret_cast<float4*>(sS)[t * 2 + 1] = v1;
        src[0] = make_float4(0.f, 0.f, 0.f, 0.f);   // replay-safe reset
        src[1] = make_float4(0.f, 0.f, 0.f, 0.f);
    }
    sW[t]       = g_W[t];
    sW[t + 256] = g_W[t + 256];
    __syncthreads();

    // einsum: out[b,n,i,c] = sum_m sS[m*128+i*32+c] * sW[m*32+n]
    {
        const int combo = t >> 1;         // (i,c)
        const int nh    = t & 1;
        const int i = combo >> 5;
        const int c = combo & 31;
        float S[16];
#pragma unroll
        for (int m = 0; m < 16; ++m) S[m] = sS[m * 128 + i * 32 + c];
#pragma unroll
        for (int n0 = 0; n0 < 16; ++n0) {
            const int n = nh * 16 + n0;
            float acc = 0.f;
#pragma unroll
            for (int m = 0; m < 16; ++m) acc += S[m] * sW[m * 32 + n];
            out[((b * 32 + n) * 4 + i) * 32 + c] = acc;
        }
    }

    // ---- counter reset handshake (replay-safe) ----
    __syncthreads();
    if (t == 0) {
        red_inc(&g_fin);
        if (b == 0) {
            while (ld_acquire(&g_fin) < 4) __nanosleep(64);
            g_cnt = 0;
            g_fin = 0;
        }
    }
}

// ---------------- launch ----------------
extern "C" void kernel_launch(void* const* d_in, const int* in_sizes, int n_in,
                              void* d_out, int out_size) {
    const float* x     = (const float*)d_in[0];
    const float* alpha = (const float*)d_in[1];
    const float* beta  = (const float*)d_in[2];
    const float* gamma = (const float*)d_in[3];
    const float* delta = (const float*)d_in[4];

    k_all<<<4100, 256>>>(x, alpha, beta, gamma, delta, (float*)d_out);
}